// round 12
// baseline (speedup 1.0000x reference)
#include <cuda_runtime.h>
#include <cuda_fp16.h>
#include <cstdint>

// ---------------------------------------------------------------------------
// DCNv2: B=8, Cin=Cout=256, H=W=64, K=3, S=1, P=1, D=1
// Pipeline:
//   0a) wconv:          weight -> fp16 [cout][k]
//   0b) xconv:          x -> fp16 image copy (gather tap source)
//   1) offset_partial:  16 channel-slices (16 ch) of 3x3 offset conv -> g_om16
//   2) offset_final:    sum + bias, sigmoid mask, sampling positions
//   3) gather:          bilinear sample (fp16 taps, fp32 math) * mask
//                       -> A fp16, K-major [k][m]
//   4) gemm:            mma.sync m16n8k16 f16, BK=32 4-stage cp.async ring,
//                       one barrier per stage
// Error budget (calibrated, each fp16 rounding = indep 2^-12):
//   A + W + tap rounding -> rel_err ~3.6e-4 (<1e-3).
// (tcgen05 unavailable: harness PTX targets compute_103, no 'a' features.
//  R9 lesson: fused gather at 1 CTA/SM exposes scattered-LDG latency; don't.)
// ---------------------------------------------------------------------------

#define BDIM   8
#define CIN    256
#define COUT   256
#define KKN    9
#define NPIX   4096
#define MTOT   32768
#define KDIM   2304

// ------------------------- scratch (device globals) ------------------------
__device__ float g_py[BDIM * KKN * NPIX];
__device__ float g_px[BDIM * KKN * NPIX];
__device__ float g_pm[BDIM * KKN * NPIX];
__device__ float g_om16[16 * 27 * MTOT];          // 56.6 MB partials
__device__ __half g_xh[(size_t)BDIM * CIN * NPIX]; // fp16 x copy (16.8 MB)
__device__ __half g_Ah[(size_t)KDIM * MTOT];       // [k][m]  (151 MB)
__device__ __half g_Wh[COUT * KDIM];               // [n][k]

// ------------------------- PTX wrappers ------------------------------------
static __device__ __forceinline__ uint32_t smem_u32(const void* p) {
    return (uint32_t)__cvta_generic_to_shared(p);
}
static __device__ __forceinline__ void ldsm_x4(uint32_t& r0, uint32_t& r1,
                                               uint32_t& r2, uint32_t& r3,
                                               uint32_t addr) {
    asm volatile("ldmatrix.sync.aligned.m8n8.x4.shared.b16 {%0,%1,%2,%3}, [%4];"
                 : "=r"(r0), "=r"(r1), "=r"(r2), "=r"(r3) : "r"(addr));
}
static __device__ __forceinline__ void ldsm_x4_t(uint32_t& r0, uint32_t& r1,
                                                 uint32_t& r2, uint32_t& r3,
                                                 uint32_t addr) {
    asm volatile("ldmatrix.sync.aligned.m8n8.x4.trans.shared.b16 {%0,%1,%2,%3}, [%4];"
                 : "=r"(r0), "=r"(r1), "=r"(r2), "=r"(r3) : "r"(addr));
}
static __device__ __forceinline__ void mma_f16(float* d, const uint32_t* a,
                                               uint32_t b0, uint32_t b1) {
    asm volatile(
        "mma.sync.aligned.m16n8k16.row.col.f32.f16.f16.f32 "
        "{%0,%1,%2,%3},{%4,%5,%6,%7},{%8,%9},{%0,%1,%2,%3};"
        : "+f"(d[0]), "+f"(d[1]), "+f"(d[2]), "+f"(d[3])
        : "r"(a[0]), "r"(a[1]), "r"(a[2]), "r"(a[3]), "r"(b0), "r"(b1));
}
static __device__ __forceinline__ void cpasync16(uint32_t dst, const void* src) {
    asm volatile("cp.async.cg.shared.global [%0], [%1], 16;"
                 :: "r"(dst), "l"(src) : "memory");
}
static __device__ __forceinline__ void cp_commit() {
    asm volatile("cp.async.commit_group;" ::: "memory");
}
static __device__ __forceinline__ void cp_wait2() {
    asm volatile("cp.async.wait_group 2;" ::: "memory");
}

// ===========================================================================
// Kernel 0a: weight -> fp16
// ===========================================================================
__global__ __launch_bounds__(256) void wconv_kernel(const float* __restrict__ w)
{
    int i = blockIdx.x * 256 + threadIdx.x;
    if (i < COUT * KDIM)
        g_Wh[i] = __float2half_rn(w[i]);
}

// ===========================================================================
// Kernel 0b: x -> fp16 copy (float4 -> half2 x2)
// ===========================================================================
__global__ __launch_bounds__(256) void xconv_kernel(const float* __restrict__ x)
{
    int i = blockIdx.x * 256 + threadIdx.x;   // over float4s: 2097152
    float4 v = reinterpret_cast<const float4*>(x)[i];
    __half2 h0 = __floats2half2_rn(v.x, v.y);
    __half2 h1 = __floats2half2_rn(v.z, v.w);
    uint2 pk;
    pk.x = *reinterpret_cast<uint32_t*>(&h0);
    pk.y = *reinterpret_cast<uint32_t*>(&h1);
    reinterpret_cast<uint2*>(g_xh)[i] = pk;
}

// ===========================================================================
// Kernel 1: offset conv partial (one 16-channel slice per blockIdx.y, 16 total)
// ===========================================================================
__global__ __launch_bounds__(256) void offset_partial_kernel(
    const float* __restrict__ x,
    const float* __restrict__ ow)
{
    const int tid = threadIdx.x;
    const int m   = blockIdx.x * 256 + tid;
    const int sl  = blockIdx.y;                 // slice 0..15
    const int b   = m >> 12;
    const int p   = m & 4095;
    const int ho  = p >> 6;
    const int wo  = p & 63;

    __shared__ __align__(16) float ws[16 * 9 * 28];

    float acc[28];
#pragma unroll
    for (int i = 0; i < 28; i++) acc[i] = 0.f;

    const bool r0ok = (ho > 0), r2ok = (ho < 63);
    const bool c0ok = (wo > 0), c2ok = (wo < 63);

    const int c0 = sl * 16;
    for (int idx = tid; idx < 27 * 16 * 9; idx += 256) {
        int oc  = idx / 144;
        int rem = idx % 144;
        int c   = rem / 9;
        int kk  = rem % 9;
        ws[c * 252 + kk * 28 + oc] = ow[(oc * CIN + c0 + c) * 9 + kk];
    }
    for (int idx = tid; idx < 144; idx += 256) {
        int c = idx / 9, kk = idx % 9;
        ws[c * 252 + kk * 28 + 27] = 0.f;
    }
    __syncthreads();

#pragma unroll 1
    for (int c = 0; c < 16; ++c) {
        const float* xc = x + ((size_t)(b * CIN + c0 + c)) * NPIX;
        float xv[9];
#pragma unroll
        for (int ki = 0; ki < 3; ki++) {
#pragma unroll
            for (int kj = 0; kj < 3; kj++) {
                bool rok = (ki == 0) ? r0ok : ((ki == 2) ? r2ok : true);
                bool cok = (kj == 0) ? c0ok : ((kj == 2) ? c2ok : true);
                int yy = ho - 1 + ki, xx = wo - 1 + kj;
                xv[ki * 3 + kj] = (rok && cok) ? xc[yy * 64 + xx] : 0.f;
            }
        }
#pragma unroll
        for (int kk = 0; kk < 9; kk++) {
            float xvk = xv[kk];
            const float4* wrow =
                reinterpret_cast<const float4*>(&ws[c * 252 + kk * 28]);
#pragma unroll
            for (int o4 = 0; o4 < 7; o4++) {
                float4 w = wrow[o4];
                acc[o4 * 4 + 0] += xvk * w.x;
                acc[o4 * 4 + 1] += xvk * w.y;
                acc[o4 * 4 + 2] += xvk * w.z;
                acc[o4 * 4 + 3] += xvk * w.w;
            }
        }
    }

#pragma unroll
    for (int i = 0; i < 27; i++)
        g_om16[((size_t)(sl * 27 + i)) * MTOT + m] = acc[i];
}

// ===========================================================================
// Kernel 2: offset finalize -> py / px / mask  (sums 16 slices)
// ===========================================================================
__global__ __launch_bounds__(256) void offset_final_kernel(
    const float* __restrict__ ob)
{
    const int m  = blockIdx.x * 256 + threadIdx.x;
    const int b  = m >> 12;
    const int p  = m & 4095;
    const int ho = p >> 6;
    const int wo = p & 63;

    float acc[27];
#pragma unroll
    for (int i = 0; i < 27; i++) {
        float s = 0.f;
#pragma unroll
        for (int sl = 0; sl < 16; sl++)
            s += g_om16[((size_t)(sl * 27 + i)) * MTOT + m];
        acc[i] = s;
    }

#pragma unroll
    for (int kk = 0; kk < 9; kk++) {
        float dy = acc[2 * kk]     + ob[2 * kk];
        float dx = acc[2 * kk + 1] + ob[2 * kk + 1];
        float mv = acc[18 + kk]    + ob[18 + kk];
        mv = 1.f / (1.f + __expf(-mv));
        int ki = kk / 3, kj = kk % 3;
        float pyv = dy + (float)(ho - 1 + ki);
        float pxv = dx + (float)(wo - 1 + kj);
        int o = ((b * 9 + kk) << 12) + p;
        g_py[o] = pyv;
        g_px[o] = pxv;
        g_pm[o] = mv;
    }
}

// ===========================================================================
// Kernel 3: bilinear gather (fp16 taps) -> A fp16, K-major g_Ah[k=c*9+kk][m]
//   c-split: blockIdx.z in {0,1}, 128 channels each
// ===========================================================================
__global__ __launch_bounds__(256) void gather_kernel()
{
    const int tid = threadIdx.x;
    const int m   = blockIdx.x * 256 + tid;
    const int kk  = blockIdx.y;
    const int cs  = blockIdx.z * 128;
    const int b   = m >> 12;
    const int p   = m & 4095;

    const int o = ((b * 9 + kk) << 12) + p;
    const float pyv = g_py[o];
    const float pxv = g_px[o];
    const float mv  = g_pm[o];

    float y0f = floorf(pyv), x0f = floorf(pxv);
    float wy1 = pyv - y0f, wx1 = pxv - x0f;
    float wy0 = 1.f - wy1, wx0 = 1.f - wx1;
    int y0 = (int)y0f, x0 = (int)x0f;
    int y1 = y0 + 1,   x1 = x0 + 1;

    float w00 = wy0 * wx0 * mv, w01 = wy0 * wx1 * mv;
    float w10 = wy1 * wx0 * mv, w11 = wy1 * wx1 * mv;
    if (y0 < 0 || y0 > 63) { w00 = 0.f; w01 = 0.f; }
    if (y1 < 0 || y1 > 63) { w10 = 0.f; w11 = 0.f; }
    if (x0 < 0 || x0 > 63) { w00 = 0.f; w10 = 0.f; }
    if (x1 < 0 || x1 > 63) { w01 = 0.f; w11 = 0.f; }

    int y0c = min(max(y0, 0), 63), y1c = min(max(y1, 0), 63);
    int x0c = min(max(x0, 0), 63), x1c = min(max(x1, 0), 63);
    const int o00 = y0c * 64 + x0c, o01 = y0c * 64 + x1c;
    const int o10 = y1c * 64 + x0c, o11 = y1c * 64 + x1c;

    const __half* xb = g_xh + (size_t)(b * CIN + cs) * NPIX;
    const size_t base = (size_t)kk * MTOT + m + (size_t)cs * 9 * MTOT;

#pragma unroll 8
    for (int c = 0; c < 128; ++c) {
        const __half* xc = xb + (size_t)c * NPIX;
        float v = w00 * __half2float(xc[o00]) + w01 * __half2float(xc[o01]) +
                  w10 * __half2float(xc[o10]) + w11 * __half2float(xc[o11]);
        g_Ah[base + (size_t)c * 9 * MTOT] = __float2half_rn(v);
    }
}

// ===========================================================================
// Kernel 4: HMMA GEMM  out[cout][m] = sum_k W[cout][k] * A[k][m]
//   Block tile 128 cout x 128 pixels, 8 warps (warp tile 64x32).
//   BK=32, 4-stage cp.async ring (18 KB/stage), ONE barrier per stage.
//   32 mma per warp per stage (two k16 sweeps of 16 independent accs).
//   Stage layout: [Ws 128 rows x 80B ([k0..15 32B][k16..31 32B][pad16])
//                 | As 32x256 swizzled]
// ===========================================================================
#define NSTG      4
#define W_RS      80
#define STG_BYTES 18432
#define OFF_B     10240
#define GEMM_SMEM (NSTG * STG_BYTES)   // 73728

__global__ __launch_bounds__(256, 1) void gemm_kernel(
    const float* __restrict__ bias,
    float* __restrict__ out)
{
    extern __shared__ __align__(1024) unsigned char smem[];
    const uint32_t sbase = smem_u32(smem);
    const int tid  = threadIdx.x;
    const int warp = tid >> 5;
    const int lane = tid & 31;
    const int mBase    = blockIdx.x * 128;   // pixel base
    const int coutBase = blockIdx.y * 128;

    // ------ staging indices ------
    const int am = tid >> 1;          // W: cout row in tile 0..127
    const int ah = tid & 1;           // W: 16B chunk parity
    const int bk = tid >> 4;          // A: k row 0..15 (also handles bk+16)
    const int bc = tid & 15;          // A: pixel chunk (8 fp16)

    const char* gW = reinterpret_cast<const char*>(
        g_Wh + (size_t)(coutBase + am) * KDIM);
    const char* gB = reinterpret_cast<const char*>(
        g_Ah + (size_t)bk * MTOT + mBase + bc * 8);

    const uint32_t aSts  = (uint32_t)(am * W_RS + ah * 16);
    const uint32_t bSts  = (uint32_t)(bk * 256 + ((bc ^ (bk & 7)) * 16));

    // ------ fragment addresses ------
    const int wm = (warp >> 2) * 64;
    const int wn = (warp & 3) * 32;
    const uint32_t aAddrBase = sbase +
        (uint32_t)((wm + (lane & 15)) * W_RS + ((lane >> 4) & 1) * 16);
    const int kRow   = (lane & 7) + ((lane >> 3) & 1) * 8;
    const int chBase = (wn >> 3) + ((lane >> 4) & 1);
    const uint32_t bOff = (uint32_t)(kRow * 256);
    const uint32_t ch0 = (uint32_t)(((chBase + 0) ^ (kRow & 7)) * 16);
    const uint32_t ch1 = (uint32_t)(((chBase + 2) ^ (kRow & 7)) * 16);

    float acc[4][4][4];
#pragma unroll
    for (int i = 0; i < 4; i++)
#pragma unroll
        for (int j = 0; j < 4; j++)
#pragma unroll
            for (int r = 0; r < 4; r++) acc[i][j][r] = 0.f;

    const int NK2 = KDIM / 32;   // 72 stages of BK=32

    auto issue = [&](int kt2, int buf) {
        const uint32_t sb = sbase + (uint32_t)(buf * STG_BYTES);
        // W: rows 0..127, 64B of k (4 chunks); this thread does chunks ah, ah+2
        const char* sw = gW + (size_t)kt2 * 64;
        cpasync16(sb + aSts,      sw + (size_t)ah * 16);
        cpasync16(sb + aSts + 32, sw + (size_t)ah * 16 + 32);
        // A: rows bk and bk+16 (same swizzle xor since (bk+16)&7 == bk&7)
        const char* sa = gB + (size_t)kt2 * 32 * MTOT * 2;
        cpasync16(sb + OFF_B + bSts,        sa);
        cpasync16(sb + OFF_B + bSts + 4096, sa + (size_t)16 * MTOT * 2);
        cp_commit();
    };

#pragma unroll
    for (int kt2 = 0; kt2 < 3; ++kt2) issue(kt2, kt2);

    for (int kt2 = 0; kt2 < NK2; ++kt2) {
        const int buf = kt2 & 3;
        cp_wait2();
        __syncthreads();   // stage kt2 visible; all warps done with buf (kt2-1)%4

        const uint32_t stg = (uint32_t)(buf * STG_BYTES);

        uint32_t wfr[2][4][4];
        uint32_t bfr[2][2][4];
#pragma unroll
        for (int half = 0; half < 2; half++) {
#pragma unroll
            for (int mi = 0; mi < 4; mi++) {
                uint32_t ad = aAddrBase + stg +
                              (uint32_t)(mi * 16 * W_RS + half * 32);
                ldsm_x4(wfr[half][mi][0], wfr[half][mi][1],
                        wfr[half][mi][2], wfr[half][mi][3], ad);
            }
            const uint32_t hbase = sbase + OFF_B + stg + bOff +
                                   (uint32_t)(half * 4096);
            ldsm_x4_t(bfr[half][0][0], bfr[half][0][1],
                      bfr[half][0][2], bfr[half][0][3], hbase + ch0);
            ldsm_x4_t(bfr[half][1][0], bfr[half][1][1],
                      bfr[half][1][2], bfr[half][1][3], hbase + ch1);
        }

        if (kt2 + 3 < NK2) issue(kt2 + 3, (kt2 + 3) & 3);
        else               cp_commit();   // keep wait_group arithmetic exact

        // ---- 32 mma: two k16 sweeps, 16 independent accumulators each ----
#pragma unroll
        for (int half = 0; half < 2; half++)
#pragma unroll
            for (int mi = 0; mi < 4; mi++)
#pragma unroll
                for (int nj = 0; nj < 2; nj++)
#pragma unroll
                    for (int h = 0; h < 2; h++)
                        mma_f16(acc[mi][nj * 2 + h], wfr[half][mi],
                                bfr[half][nj][2 * h], bfr[half][nj][2 * h + 1]);
    }

    // ---- epilogue ----
    const int g = lane >> 2;
    const int t = lane & 3;
    const int b    = mBase >> 12;
    const int pbB  = (mBase & 4095) + wn;
    float* outB = out + (size_t)b * COUT * NPIX;

#pragma unroll
    for (int mi = 0; mi < 4; mi++) {
        int c0 = coutBase + wm + mi * 16 + g;
        int c1 = c0 + 8;
        float bv0 = __ldg(&bias[c0]);
        float bv1 = __ldg(&bias[c1]);
        float* r0 = outB + (size_t)c0 * NPIX + pbB;
        float* r1 = outB + (size_t)c1 * NPIX + pbB;
#pragma unroll
        for (int ni = 0; ni < 4; ni++) {
            int pcol = ni * 8 + 2 * t;
            float2 v0 = make_float2(acc[mi][ni][0] + bv0, acc[mi][ni][1] + bv0);
            float2 v1 = make_float2(acc[mi][ni][2] + bv1, acc[mi][ni][3] + bv1);
            *reinterpret_cast<float2*>(r0 + pcol) = v0;
            *reinterpret_cast<float2*>(r1 + pcol) = v1;
        }
    }
}

// ===========================================================================
extern "C" void kernel_launch(void* const* d_in, const int* in_sizes, int n_in,
                              void* d_out, int out_size)
{
    const float* x        = (const float*)d_in[0];
    const float* weight   = (const float*)d_in[1];
    const float* bias     = (const float*)d_in[2];
    const float* offset_w = (const float*)d_in[3];
    const float* offset_b = (const float*)d_in[4];
    float* out = (float*)d_out;

    cudaFuncSetAttribute(gemm_kernel,
                         cudaFuncAttributeMaxDynamicSharedMemorySize, GEMM_SMEM);

    // 0a) weight -> fp16
    wconv_kernel<<<(COUT * KDIM + 255) / 256, 256>>>(weight);

    // 0b) x -> fp16 copy
    xconv_kernel<<<(BDIM * CIN * NPIX / 4) / 256, 256>>>(x);

    // 1) offset conv partials (16 channel slices of 16)
    dim3 ogrid(MTOT / 256, 16);
    offset_partial_kernel<<<ogrid, 256>>>(x, offset_w);

    // 2) finalize offsets
    offset_final_kernel<<<MTOT / 256, 256>>>(offset_b);

    // 3) bilinear gather (fp16 taps) -> fp16 A matrix (c-split x2)
    dim3 ggrid(MTOT / 256, KKN, 2);
    gather_kernel<<<ggrid, 256>>>();

    // 4) HMMA GEMM + bias (BK=32 cp.async pipelined)
    dim3 mgrid(MTOT / 128, COUT / 128);
    gemm_kernel<<<mgrid, 256, GEMM_SMEM>>>(bias, out);
}

// round 13
// speedup vs baseline: 1.0231x; 1.0231x over previous
#include <cuda_runtime.h>
#include <cuda_fp16.h>
#include <cstdint>

// ---------------------------------------------------------------------------
// DCNv2: B=8, Cin=Cout=256, H=W=64, K=3, S=1, P=1, D=1
// Pipeline (R11 structure + fp16-tap gather only):
//   0a) wconv:          weight -> fp16 [cout][k]
//   0b) xconv:          x -> fp16 image copy (gather tap source)
//   1) offset_partial:  8 channel-slices (32 ch) of 3x3 offset conv -> g_om8
//   2) offset_final:    sum + bias, sigmoid mask, sampling positions
//   3) gather:          bilinear sample (fp16 taps, fp32 math) * mask
//                       -> A fp16, K-major [k][m]
//   4) gemm:            mma.sync m16n8k16 f16 single term, BK=16,
//                       6-stage cp.async ring (R11-proven, ~170us)
// Error budget (calibrated): A + W + tap fp16 roundings -> rel_err 3.59e-4.
// (tcgen05 unavailable: harness PTX targets compute_103, no 'a' features.
//  R9: fused gather at 1 CTA/SM exposes scattered-LDG latency.
//  R12: 16-slice offset split + BK=32 ring regressed; reverted.)
// ---------------------------------------------------------------------------

#define BDIM   8
#define CIN    256
#define COUT   256
#define KKN    9
#define NPIX   4096
#define MTOT   32768
#define KDIM   2304

// ------------------------- scratch (device globals) ------------------------
__device__ float g_py[BDIM * KKN * NPIX];
__device__ float g_px[BDIM * KKN * NPIX];
__device__ float g_pm[BDIM * KKN * NPIX];
__device__ float g_om8[8 * 27 * MTOT];
__device__ __half g_xh[(size_t)BDIM * CIN * NPIX]; // fp16 x copy (16.8 MB)
__device__ __half g_Ah[(size_t)KDIM * MTOT];       // [k][m]  (151 MB)
__device__ __half g_Wh[COUT * KDIM];               // [n][k]

// ------------------------- PTX wrappers ------------------------------------
static __device__ __forceinline__ uint32_t smem_u32(const void* p) {
    return (uint32_t)__cvta_generic_to_shared(p);
}
static __device__ __forceinline__ void ldsm_x4(uint32_t& r0, uint32_t& r1,
                                               uint32_t& r2, uint32_t& r3,
                                               uint32_t addr) {
    asm volatile("ldmatrix.sync.aligned.m8n8.x4.shared.b16 {%0,%1,%2,%3}, [%4];"
                 : "=r"(r0), "=r"(r1), "=r"(r2), "=r"(r3) : "r"(addr));
}
static __device__ __forceinline__ void ldsm_x4_t(uint32_t& r0, uint32_t& r1,
                                                 uint32_t& r2, uint32_t& r3,
                                                 uint32_t addr) {
    asm volatile("ldmatrix.sync.aligned.m8n8.x4.trans.shared.b16 {%0,%1,%2,%3}, [%4];"
                 : "=r"(r0), "=r"(r1), "=r"(r2), "=r"(r3) : "r"(addr));
}
static __device__ __forceinline__ void mma_f16(float* d, const uint32_t* a,
                                               uint32_t b0, uint32_t b1) {
    asm volatile(
        "mma.sync.aligned.m16n8k16.row.col.f32.f16.f16.f32 "
        "{%0,%1,%2,%3},{%4,%5,%6,%7},{%8,%9},{%0,%1,%2,%3};"
        : "+f"(d[0]), "+f"(d[1]), "+f"(d[2]), "+f"(d[3])
        : "r"(a[0]), "r"(a[1]), "r"(a[2]), "r"(a[3]), "r"(b0), "r"(b1));
}
static __device__ __forceinline__ void cpasync16(uint32_t dst, const void* src) {
    asm volatile("cp.async.cg.shared.global [%0], [%1], 16;"
                 :: "r"(dst), "l"(src) : "memory");
}
static __device__ __forceinline__ void cp_commit() {
    asm volatile("cp.async.commit_group;" ::: "memory");
}
static __device__ __forceinline__ void cp_wait4() {
    asm volatile("cp.async.wait_group 4;" ::: "memory");
}

// ===========================================================================
// Kernel 0a: weight -> fp16
// ===========================================================================
__global__ __launch_bounds__(256) void wconv_kernel(const float* __restrict__ w)
{
    int i = blockIdx.x * 256 + threadIdx.x;
    if (i < COUT * KDIM)
        g_Wh[i] = __float2half_rn(w[i]);
}

// ===========================================================================
// Kernel 0b: x -> fp16 copy (float4 -> half2 x2)
// ===========================================================================
__global__ __launch_bounds__(256) void xconv_kernel(const float* __restrict__ x)
{
    int i = blockIdx.x * 256 + threadIdx.x;   // over float4s: 2097152
    float4 v = reinterpret_cast<const float4*>(x)[i];
    __half2 h0 = __floats2half2_rn(v.x, v.y);
    __half2 h1 = __floats2half2_rn(v.z, v.w);
    uint2 pk;
    pk.x = *reinterpret_cast<uint32_t*>(&h0);
    pk.y = *reinterpret_cast<uint32_t*>(&h1);
    reinterpret_cast<uint2*>(g_xh)[i] = pk;
}

// ===========================================================================
// Kernel 1: offset conv partial (one 32-channel slice per blockIdx.y, 8 total)
// ===========================================================================
__global__ __launch_bounds__(256) void offset_partial_kernel(
    const float* __restrict__ x,
    const float* __restrict__ ow)
{
    const int tid = threadIdx.x;
    const int m   = blockIdx.x * 256 + tid;
    const int sl  = blockIdx.y;                 // slice 0..7
    const int b   = m >> 12;
    const int p   = m & 4095;
    const int ho  = p >> 6;
    const int wo  = p & 63;

    __shared__ __align__(16) float ws[32 * 9 * 28];

    float acc[28];
#pragma unroll
    for (int i = 0; i < 28; i++) acc[i] = 0.f;

    const bool r0ok = (ho > 0), r2ok = (ho < 63);
    const bool c0ok = (wo > 0), c2ok = (wo < 63);

    const int c0 = sl * 32;
    for (int idx = tid; idx < 27 * 32 * 9; idx += 256) {
        int oc  = idx / 288;
        int rem = idx % 288;
        int c   = rem / 9;
        int kk  = rem % 9;
        ws[c * 252 + kk * 28 + oc] = ow[(oc * CIN + c0 + c) * 9 + kk];
    }
    for (int idx = tid; idx < 288; idx += 256) {
        int c = idx / 9, kk = idx % 9;
        ws[c * 252 + kk * 28 + 27] = 0.f;
    }
    __syncthreads();

#pragma unroll 1
    for (int c = 0; c < 32; ++c) {
        const float* xc = x + ((size_t)(b * CIN + c0 + c)) * NPIX;
        float xv[9];
#pragma unroll
        for (int ki = 0; ki < 3; ki++) {
#pragma unroll
            for (int kj = 0; kj < 3; kj++) {
                bool rok = (ki == 0) ? r0ok : ((ki == 2) ? r2ok : true);
                bool cok = (kj == 0) ? c0ok : ((kj == 2) ? c2ok : true);
                int yy = ho - 1 + ki, xx = wo - 1 + kj;
                xv[ki * 3 + kj] = (rok && cok) ? xc[yy * 64 + xx] : 0.f;
            }
        }
#pragma unroll
        for (int kk = 0; kk < 9; kk++) {
            float xvk = xv[kk];
            const float4* wrow =
                reinterpret_cast<const float4*>(&ws[c * 252 + kk * 28]);
#pragma unroll
            for (int o4 = 0; o4 < 7; o4++) {
                float4 w = wrow[o4];
                acc[o4 * 4 + 0] += xvk * w.x;
                acc[o4 * 4 + 1] += xvk * w.y;
                acc[o4 * 4 + 2] += xvk * w.z;
                acc[o4 * 4 + 3] += xvk * w.w;
            }
        }
    }

#pragma unroll
    for (int i = 0; i < 27; i++)
        g_om8[((size_t)(sl * 27 + i)) * MTOT + m] = acc[i];
}

// ===========================================================================
// Kernel 2: offset finalize -> py / px / mask  (sums 8 slices)
// ===========================================================================
__global__ __launch_bounds__(256) void offset_final_kernel(
    const float* __restrict__ ob)
{
    const int m  = blockIdx.x * 256 + threadIdx.x;
    const int b  = m >> 12;
    const int p  = m & 4095;
    const int ho = p >> 6;
    const int wo = p & 63;

    float acc[27];
#pragma unroll
    for (int i = 0; i < 27; i++) {
        float s = 0.f;
#pragma unroll
        for (int sl = 0; sl < 8; sl++)
            s += g_om8[((size_t)(sl * 27 + i)) * MTOT + m];
        acc[i] = s;
    }

#pragma unroll
    for (int kk = 0; kk < 9; kk++) {
        float dy = acc[2 * kk]     + ob[2 * kk];
        float dx = acc[2 * kk + 1] + ob[2 * kk + 1];
        float mv = acc[18 + kk]    + ob[18 + kk];
        mv = 1.f / (1.f + __expf(-mv));
        int ki = kk / 3, kj = kk % 3;
        float pyv = dy + (float)(ho - 1 + ki);
        float pxv = dx + (float)(wo - 1 + kj);
        int o = ((b * 9 + kk) << 12) + p;
        g_py[o] = pyv;
        g_px[o] = pxv;
        g_pm[o] = mv;
    }
}

// ===========================================================================
// Kernel 3: bilinear gather (fp16 taps) -> A fp16, K-major g_Ah[k=c*9+kk][m]
//   c-split: blockIdx.z in {0,1}, 128 channels each
// ===========================================================================
__global__ __launch_bounds__(256) void gather_kernel()
{
    const int tid = threadIdx.x;
    const int m   = blockIdx.x * 256 + tid;
    const int kk  = blockIdx.y;
    const int cs  = blockIdx.z * 128;
    const int b   = m >> 12;
    const int p   = m & 4095;

    const int o = ((b * 9 + kk) << 12) + p;
    const float pyv = g_py[o];
    const float pxv = g_px[o];
    const float mv  = g_pm[o];

    float y0f = floorf(pyv), x0f = floorf(pxv);
    float wy1 = pyv - y0f, wx1 = pxv - x0f;
    float wy0 = 1.f - wy1, wx0 = 1.f - wx1;
    int y0 = (int)y0f, x0 = (int)x0f;
    int y1 = y0 + 1,   x1 = x0 + 1;

    float w00 = wy0 * wx0 * mv, w01 = wy0 * wx1 * mv;
    float w10 = wy1 * wx0 * mv, w11 = wy1 * wx1 * mv;
    if (y0 < 0 || y0 > 63) { w00 = 0.f; w01 = 0.f; }
    if (y1 < 0 || y1 > 63) { w10 = 0.f; w11 = 0.f; }
    if (x0 < 0 || x0 > 63) { w00 = 0.f; w10 = 0.f; }
    if (x1 < 0 || x1 > 63) { w01 = 0.f; w11 = 0.f; }

    int y0c = min(max(y0, 0), 63), y1c = min(max(y1, 0), 63);
    int x0c = min(max(x0, 0), 63), x1c = min(max(x1, 0), 63);
    const int o00 = y0c * 64 + x0c, o01 = y0c * 64 + x1c;
    const int o10 = y1c * 64 + x0c, o11 = y1c * 64 + x1c;

    const __half* xb = g_xh + (size_t)(b * CIN + cs) * NPIX;
    const size_t base = (size_t)kk * MTOT + m + (size_t)cs * 9 * MTOT;

#pragma unroll 8
    for (int c = 0; c < 128; ++c) {
        const __half* xc = xb + (size_t)c * NPIX;
        float v = w00 * __half2float(xc[o00]) + w01 * __half2float(xc[o01]) +
                  w10 * __half2float(xc[o10]) + w11 * __half2float(xc[o11]);
        g_Ah[base + (size_t)c * 9 * MTOT] = __float2half_rn(v);
    }
}

// ===========================================================================
// Kernel 4: HMMA GEMM  out[cout][m] = sum_k W[cout][k] * A[k][m]
//   Block tile 128 cout x 128 pixels, 8 warps (warp tile 64x32).
//   6-stage cp.async ring (BK=16, 10 KB/stage), one barrier per stage.
//   16 mma per warp per stage, single fp16 term. (R11-proven)
// ===========================================================================
#define NSTG      6
#define W_RS      48
#define STG_BYTES 10240
#define OFF_B     6144
#define GEMM_SMEM (NSTG * STG_BYTES)   // 61440

__global__ __launch_bounds__(256, 1) void gemm_kernel(
    const float* __restrict__ bias,
    float* __restrict__ out)
{
    extern __shared__ __align__(1024) unsigned char smem[];
    const uint32_t sbase = smem_u32(smem);
    const int tid  = threadIdx.x;
    const int warp = tid >> 5;
    const int lane = tid & 31;
    const int mBase    = blockIdx.x * 128;   // pixel base
    const int coutBase = blockIdx.y * 128;

    // ------ staging indices ------
    const int am = tid >> 1;          // W: cout row in tile 0..127
    const int ah = tid & 1;           // W: k half (8 fp16 = 16B)
    const int bk = tid >> 4;          // A: k row 0..15
    const int bc = tid & 15;          // A: pixel chunk (8 fp16)

    const char* gW = reinterpret_cast<const char*>(
        g_Wh + (size_t)(coutBase + am) * KDIM);
    const char* gB = reinterpret_cast<const char*>(
        g_Ah + (size_t)bk * MTOT + mBase + bc * 8);

    const uint32_t aSts = (uint32_t)(am * W_RS + ah * 16);
    const uint32_t bSts = (uint32_t)(bk * 256 + ((bc ^ (bk & 7)) * 16));

    // ------ fragment addresses ------
    const int wm = (warp >> 2) * 64;
    const int wn = (warp & 3) * 32;
    const uint32_t aAddrBase = sbase +
        (uint32_t)((wm + (lane & 15)) * W_RS + ((lane >> 4) & 1) * 16);
    const int kRow   = (lane & 7) + ((lane >> 3) & 1) * 8;
    const int chBase = (wn >> 3) + ((lane >> 4) & 1);
    const uint32_t bOff = (uint32_t)(kRow * 256);
    const uint32_t ch0 = (uint32_t)(((chBase + 0) ^ (kRow & 7)) * 16);
    const uint32_t ch1 = (uint32_t)(((chBase + 2) ^ (kRow & 7)) * 16);

    float acc[4][4][4];
#pragma unroll
    for (int i = 0; i < 4; i++)
#pragma unroll
        for (int j = 0; j < 4; j++)
#pragma unroll
            for (int r = 0; r < 4; r++) acc[i][j][r] = 0.f;

    const int NK = KDIM / 16;   // 144

    auto issueW = [&](int kt, int buf) {
        const uint32_t sb = sbase + (uint32_t)(buf * STG_BYTES);
        cpasync16(sb + aSts,         gW + (size_t)kt * 32 + (size_t)ah * 16);
        cpasync16(sb + OFF_B + bSts, gB + (size_t)kt * 16 * MTOT * 2);
        cp_commit();
    };

#pragma unroll
    for (int kt = 0; kt < 5; ++kt) issueW(kt, kt);

    for (int kt = 0; kt < NK; ++kt) {
        const int buf = kt % NSTG;
        cp_wait4();
        __syncthreads();

        const uint32_t stg = (uint32_t)(buf * STG_BYTES);

        uint32_t wfr[4][4];
#pragma unroll
        for (int mi = 0; mi < 4; mi++) {
            uint32_t ad = aAddrBase + stg + (uint32_t)(mi * 16 * W_RS);
            ldsm_x4(wfr[mi][0], wfr[mi][1], wfr[mi][2], wfr[mi][3], ad);
        }
        uint32_t bfr[2][4];
        {
            const uint32_t hbase = sbase + OFF_B + stg + bOff;
            ldsm_x4_t(bfr[0][0], bfr[0][1], bfr[0][2], bfr[0][3], hbase + ch0);
            ldsm_x4_t(bfr[1][0], bfr[1][1], bfr[1][2], bfr[1][3], hbase + ch1);
        }

        if (kt + 5 < NK) issueW(kt + 5, (kt + 5) % NSTG);
        else             cp_commit();

        // ---- 16 mma, all independent accumulators ----
#pragma unroll
        for (int mi = 0; mi < 4; mi++)
#pragma unroll
            for (int nj = 0; nj < 2; nj++)
#pragma unroll
                for (int h = 0; h < 2; h++)
                    mma_f16(acc[mi][nj * 2 + h], wfr[mi],
                            bfr[nj][2 * h], bfr[nj][2 * h + 1]);

        __syncthreads();
    }

    // ---- epilogue ----
    const int g = lane >> 2;
    const int t = lane & 3;
    const int b    = mBase >> 12;
    const int pbB  = (mBase & 4095) + wn;
    float* outB = out + (size_t)b * COUT * NPIX;

#pragma unroll
    for (int mi = 0; mi < 4; mi++) {
        int c0 = coutBase + wm + mi * 16 + g;
        int c1 = c0 + 8;
        float bv0 = __ldg(&bias[c0]);
        float bv1 = __ldg(&bias[c1]);
        float* r0 = outB + (size_t)c0 * NPIX + pbB;
        float* r1 = outB + (size_t)c1 * NPIX + pbB;
#pragma unroll
        for (int ni = 0; ni < 4; ni++) {
            int pcol = ni * 8 + 2 * t;
            float2 v0 = make_float2(acc[mi][ni][0] + bv0, acc[mi][ni][1] + bv0);
            float2 v1 = make_float2(acc[mi][ni][2] + bv1, acc[mi][ni][3] + bv1);
            *reinterpret_cast<float2*>(r0 + pcol) = v0;
            *reinterpret_cast<float2*>(r1 + pcol) = v1;
        }
    }
}

// ===========================================================================
extern "C" void kernel_launch(void* const* d_in, const int* in_sizes, int n_in,
                              void* d_out, int out_size)
{
    const float* x        = (const float*)d_in[0];
    const float* weight   = (const float*)d_in[1];
    const float* bias     = (const float*)d_in[2];
    const float* offset_w = (const float*)d_in[3];
    const float* offset_b = (const float*)d_in[4];
    float* out = (float*)d_out;

    cudaFuncSetAttribute(gemm_kernel,
                         cudaFuncAttributeMaxDynamicSharedMemorySize, GEMM_SMEM);

    // 0a) weight -> fp16
    wconv_kernel<<<(COUT * KDIM + 255) / 256, 256>>>(weight);

    // 0b) x -> fp16 copy
    xconv_kernel<<<(BDIM * CIN * NPIX / 4) / 256, 256>>>(x);

    // 1) offset conv partials (8 channel slices of 32)
    dim3 ogrid(MTOT / 256, 8);
    offset_partial_kernel<<<ogrid, 256>>>(x, offset_w);

    // 2) finalize offsets
    offset_final_kernel<<<MTOT / 256, 256>>>(offset_b);

    // 3) bilinear gather (fp16 taps) -> fp16 A matrix (c-split x2)
    dim3 ggrid(MTOT / 256, KKN, 2);
    gather_kernel<<<ggrid, 256>>>();

    // 4) HMMA GEMM + bias (BK=16, 6-stage, R11-proven)
    dim3 mgrid(MTOT / 128, COUT / 128);
    gemm_kernel<<<mgrid, 256, GEMM_SMEM>>>(bias, out);
}

// round 14
// speedup vs baseline: 1.0407x; 1.0172x over previous
#include <cuda_runtime.h>
#include <cuda_fp16.h>
#include <cstdint>

// ---------------------------------------------------------------------------
// DCNv2: B=8, Cin=Cout=256, H=W=64, K=3, S=1, P=1, D=1
// Pipeline (R11 base + offset_final kk-split + GEMM single-barrier):
//   0) wconv:           weight -> fp16 [cout][k]
//   1) offset_partial:  8 channel-slices (32 ch) of 3x3 offset conv -> g_om8
//   2) offset_final:    per-(m,kk) sum of ONLY the 3 needed channels (grid x9)
//   3) gather:          bilinear sample (fp32 taps) * mask -> A fp16 [k][m]
//   4) gemm:            mma.sync m16n8k16 f16 single term, BK=16,
//                       6-stage cp.async ring, ONE barrier per stage
// Error budget (calibrated): A + W fp16 roundings -> rel_err 2.93e-4.
// (tcgen05 unavailable: harness PTX targets compute_103.
//  R9: fused gather at 1 CTA/SM exposes scattered-LDG latency.
//  R12: 16-slice offset split + BK=32 ring regressed.
//  R13: fp16-tap gather neutral (LDG-count bound, not byte bound); reverted.)
// ---------------------------------------------------------------------------

#define BDIM   8
#define CIN    256
#define COUT   256
#define KKN    9
#define NPIX   4096
#define MTOT   32768
#define KDIM   2304

// ------------------------- scratch (device globals) ------------------------
__device__ float g_py[BDIM * KKN * NPIX];
__device__ float g_px[BDIM * KKN * NPIX];
__device__ float g_pm[BDIM * KKN * NPIX];
__device__ float g_om8[8 * 27 * MTOT];
__device__ __half g_Ah[(size_t)KDIM * MTOT];       // [k][m]  (151 MB)
__device__ __half g_Wh[COUT * KDIM];               // [n][k]

// ------------------------- PTX wrappers ------------------------------------
static __device__ __forceinline__ uint32_t smem_u32(const void* p) {
    return (uint32_t)__cvta_generic_to_shared(p);
}
static __device__ __forceinline__ void ldsm_x4(uint32_t& r0, uint32_t& r1,
                                               uint32_t& r2, uint32_t& r3,
                                               uint32_t addr) {
    asm volatile("ldmatrix.sync.aligned.m8n8.x4.shared.b16 {%0,%1,%2,%3}, [%4];"
                 : "=r"(r0), "=r"(r1), "=r"(r2), "=r"(r3) : "r"(addr));
}
static __device__ __forceinline__ void ldsm_x4_t(uint32_t& r0, uint32_t& r1,
                                                 uint32_t& r2, uint32_t& r3,
                                                 uint32_t addr) {
    asm volatile("ldmatrix.sync.aligned.m8n8.x4.trans.shared.b16 {%0,%1,%2,%3}, [%4];"
                 : "=r"(r0), "=r"(r1), "=r"(r2), "=r"(r3) : "r"(addr));
}
static __device__ __forceinline__ void mma_f16(float* d, const uint32_t* a,
                                               uint32_t b0, uint32_t b1) {
    asm volatile(
        "mma.sync.aligned.m16n8k16.row.col.f32.f16.f16.f32 "
        "{%0,%1,%2,%3},{%4,%5,%6,%7},{%8,%9},{%0,%1,%2,%3};"
        : "+f"(d[0]), "+f"(d[1]), "+f"(d[2]), "+f"(d[3])
        : "r"(a[0]), "r"(a[1]), "r"(a[2]), "r"(a[3]), "r"(b0), "r"(b1));
}
static __device__ __forceinline__ void cpasync16(uint32_t dst, const void* src) {
    asm volatile("cp.async.cg.shared.global [%0], [%1], 16;"
                 :: "r"(dst), "l"(src) : "memory");
}
static __device__ __forceinline__ void cp_commit() {
    asm volatile("cp.async.commit_group;" ::: "memory");
}
static __device__ __forceinline__ void cp_wait4() {
    asm volatile("cp.async.wait_group 4;" ::: "memory");
}

// ===========================================================================
// Kernel 0: weight -> fp16
// ===========================================================================
__global__ __launch_bounds__(256) void wconv_kernel(const float* __restrict__ w)
{
    int i = blockIdx.x * 256 + threadIdx.x;
    if (i < COUT * KDIM)
        g_Wh[i] = __float2half_rn(w[i]);
}

// ===========================================================================
// Kernel 1: offset conv partial (one 32-channel slice per blockIdx.y, 8 total)
// ===========================================================================
__global__ __launch_bounds__(256) void offset_partial_kernel(
    const float* __restrict__ x,
    const float* __restrict__ ow)
{
    const int tid = threadIdx.x;
    const int m   = blockIdx.x * 256 + tid;
    const int sl  = blockIdx.y;                 // slice 0..7
    const int b   = m >> 12;
    const int p   = m & 4095;
    const int ho  = p >> 6;
    const int wo  = p & 63;

    __shared__ __align__(16) float ws[32 * 9 * 28];

    float acc[28];
#pragma unroll
    for (int i = 0; i < 28; i++) acc[i] = 0.f;

    const bool r0ok = (ho > 0), r2ok = (ho < 63);
    const bool c0ok = (wo > 0), c2ok = (wo < 63);

    const int c0 = sl * 32;
    for (int idx = tid; idx < 27 * 32 * 9; idx += 256) {
        int oc  = idx / 288;
        int rem = idx % 288;
        int c   = rem / 9;
        int kk  = rem % 9;
        ws[c * 252 + kk * 28 + oc] = ow[(oc * CIN + c0 + c) * 9 + kk];
    }
    for (int idx = tid; idx < 288; idx += 256) {
        int c = idx / 9, kk = idx % 9;
        ws[c * 252 + kk * 28 + 27] = 0.f;
    }
    __syncthreads();

#pragma unroll 1
    for (int c = 0; c < 32; ++c) {
        const float* xc = x + ((size_t)(b * CIN + c0 + c)) * NPIX;
        float xv[9];
#pragma unroll
        for (int ki = 0; ki < 3; ki++) {
#pragma unroll
            for (int kj = 0; kj < 3; kj++) {
                bool rok = (ki == 0) ? r0ok : ((ki == 2) ? r2ok : true);
                bool cok = (kj == 0) ? c0ok : ((kj == 2) ? c2ok : true);
                int yy = ho - 1 + ki, xx = wo - 1 + kj;
                xv[ki * 3 + kj] = (rok && cok) ? xc[yy * 64 + xx] : 0.f;
            }
        }
#pragma unroll
        for (int kk = 0; kk < 9; kk++) {
            float xvk = xv[kk];
            const float4* wrow =
                reinterpret_cast<const float4*>(&ws[c * 252 + kk * 28]);
#pragma unroll
            for (int o4 = 0; o4 < 7; o4++) {
                float4 w = wrow[o4];
                acc[o4 * 4 + 0] += xvk * w.x;
                acc[o4 * 4 + 1] += xvk * w.y;
                acc[o4 * 4 + 2] += xvk * w.z;
                acc[o4 * 4 + 3] += xvk * w.w;
            }
        }
    }

#pragma unroll
    for (int i = 0; i < 27; i++)
        g_om8[((size_t)(sl * 27 + i)) * MTOT + m] = acc[i];
}

// ===========================================================================
// Kernel 2: offset finalize (kk-split: grid 128 x 9)
//   Each thread handles one (m, kk): needs only channels 2kk, 2kk+1, 18+kk.
// ===========================================================================
__global__ __launch_bounds__(256) void offset_final_kernel(
    const float* __restrict__ ob)
{
    const int m  = blockIdx.x * 256 + threadIdx.x;
    const int kk = blockIdx.y;
    const int b  = m >> 12;
    const int p  = m & 4095;
    const int ho = p >> 6;
    const int wo = p & 63;

    float sdy = 0.f, sdx = 0.f, smv = 0.f;
#pragma unroll
    for (int sl = 0; sl < 8; sl++) {
        const float* base = g_om8 + (size_t)sl * 27 * MTOT + m;
        sdy += base[(size_t)(2 * kk)     * MTOT];
        sdx += base[(size_t)(2 * kk + 1) * MTOT];
        smv += base[(size_t)(18 + kk)    * MTOT];
    }

    float dy = sdy + ob[2 * kk];
    float dx = sdx + ob[2 * kk + 1];
    float mv = smv + ob[18 + kk];
    mv = 1.f / (1.f + __expf(-mv));
    int ki = kk / 3, kj = kk % 3;
    float pyv = dy + (float)(ho - 1 + ki);
    float pxv = dx + (float)(wo - 1 + kj);
    int o = ((b * 9 + kk) << 12) + p;
    g_py[o] = pyv;
    g_px[o] = pxv;
    g_pm[o] = mv;
}

// ===========================================================================
// Kernel 3: bilinear gather -> A fp16, K-major g_Ah[k = c*9+kk][m]
//   c-split: blockIdx.z in {0,1}, 128 channels each  (R11-proven, 99us)
// ===========================================================================
__global__ __launch_bounds__(256) void gather_kernel(const float* __restrict__ x)
{
    const int tid = threadIdx.x;
    const int m   = blockIdx.x * 256 + tid;
    const int kk  = blockIdx.y;
    const int cs  = blockIdx.z * 128;
    const int b   = m >> 12;
    const int p   = m & 4095;

    const int o = ((b * 9 + kk) << 12) + p;
    const float pyv = g_py[o];
    const float pxv = g_px[o];
    const float mv  = g_pm[o];

    float y0f = floorf(pyv), x0f = floorf(pxv);
    float wy1 = pyv - y0f, wx1 = pxv - x0f;
    float wy0 = 1.f - wy1, wx0 = 1.f - wx1;
    int y0 = (int)y0f, x0 = (int)x0f;
    int y1 = y0 + 1,   x1 = x0 + 1;

    float w00 = wy0 * wx0 * mv, w01 = wy0 * wx1 * mv;
    float w10 = wy1 * wx0 * mv, w11 = wy1 * wx1 * mv;
    if (y0 < 0 || y0 > 63) { w00 = 0.f; w01 = 0.f; }
    if (y1 < 0 || y1 > 63) { w10 = 0.f; w11 = 0.f; }
    if (x0 < 0 || x0 > 63) { w00 = 0.f; w10 = 0.f; }
    if (x1 < 0 || x1 > 63) { w01 = 0.f; w11 = 0.f; }

    int y0c = min(max(y0, 0), 63), y1c = min(max(y1, 0), 63);
    int x0c = min(max(x0, 0), 63), x1c = min(max(x1, 0), 63);
    const int o00 = y0c * 64 + x0c, o01 = y0c * 64 + x1c;
    const int o10 = y1c * 64 + x0c, o11 = y1c * 64 + x1c;

    const float* xb = x + (size_t)(b * CIN + cs) * NPIX;
    const size_t base = (size_t)kk * MTOT + m + (size_t)cs * 9 * MTOT;

#pragma unroll 8
    for (int c = 0; c < 128; ++c) {
        const float* xc = xb + (size_t)c * NPIX;
        float v = w00 * xc[o00] + w01 * xc[o01] +
                  w10 * xc[o10] + w11 * xc[o11];
        g_Ah[base + (size_t)c * 9 * MTOT] = __float2half_rn(v);
    }
}

// ===========================================================================
// Kernel 4: HMMA GEMM  out[cout][m] = sum_k W[cout][k] * A[k][m]
//   Block tile 128 cout x 128 pixels, 8 warps (warp tile 64x32).
//   6-stage cp.async ring (BK=16, 10 KB/stage), ONE barrier per stage.
//   Safety of single barrier: issue(kt+5) writes buf (kt-1)%6; a warp past
//   the top barrier of kt implies all warps completed their ldsm of kt-1.
//   16 mma per warp per stage, single fp16 term.
// ===========================================================================
#define NSTG      6
#define W_RS      48
#define STG_BYTES 10240
#define OFF_B     6144
#define GEMM_SMEM (NSTG * STG_BYTES)   // 61440

__global__ __launch_bounds__(256, 1) void gemm_kernel(
    const float* __restrict__ bias,
    float* __restrict__ out)
{
    extern __shared__ __align__(1024) unsigned char smem[];
    const uint32_t sbase = smem_u32(smem);
    const int tid  = threadIdx.x;
    const int warp = tid >> 5;
    const int lane = tid & 31;
    const int mBase    = blockIdx.x * 128;   // pixel base
    const int coutBase = blockIdx.y * 128;

    // ------ staging indices ------
    const int am = tid >> 1;          // W: cout row in tile 0..127
    const int ah = tid & 1;           // W: k half (8 fp16 = 16B)
    const int bk = tid >> 4;          // A: k row 0..15
    const int bc = tid & 15;          // A: pixel chunk (8 fp16)

    const char* gW = reinterpret_cast<const char*>(
        g_Wh + (size_t)(coutBase + am) * KDIM);
    const char* gB = reinterpret_cast<const char*>(
        g_Ah + (size_t)bk * MTOT + mBase + bc * 8);

    const uint32_t aSts = (uint32_t)(am * W_RS + ah * 16);
    const uint32_t bSts = (uint32_t)(bk * 256 + ((bc ^ (bk & 7)) * 16));

    // ------ fragment addresses ------
    const int wm = (warp >> 2) * 64;
    const int wn = (warp & 3) * 32;
    const uint32_t aAddrBase = sbase +
        (uint32_t)((wm + (lane & 15)) * W_RS + ((lane >> 4) & 1) * 16);
    const int kRow   = (lane & 7) + ((lane >> 3) & 1) * 8;
    const int chBase = (wn >> 3) + ((lane >> 4) & 1);
    const uint32_t bOff = (uint32_t)(kRow * 256);
    const uint32_t ch0 = (uint32_t)(((chBase + 0) ^ (kRow & 7)) * 16);
    const uint32_t ch1 = (uint32_t)(((chBase + 2) ^ (kRow & 7)) * 16);

    float acc[4][4][4];
#pragma unroll
    for (int i = 0; i < 4; i++)
#pragma unroll
        for (int j = 0; j < 4; j++)
#pragma unroll
            for (int r = 0; r < 4; r++) acc[i][j][r] = 0.f;

    const int NK = KDIM / 16;   // 144

    auto issueW = [&](int kt, int buf) {
        const uint32_t sb = sbase + (uint32_t)(buf * STG_BYTES);
        cpasync16(sb + aSts,         gW + (size_t)kt * 32 + (size_t)ah * 16);
        cpasync16(sb + OFF_B + bSts, gB + (size_t)kt * 16 * MTOT * 2);
        cp_commit();
    };

#pragma unroll
    for (int kt = 0; kt < 5; ++kt) issueW(kt, kt);

    for (int kt = 0; kt < NK; ++kt) {
        const int buf = kt % NSTG;
        cp_wait4();
        __syncthreads();   // sole barrier: orders both ring reuse and A-arrival

        const uint32_t stg = (uint32_t)(buf * STG_BYTES);

        uint32_t wfr[4][4];
#pragma unroll
        for (int mi = 0; mi < 4; mi++) {
            uint32_t ad = aAddrBase + stg + (uint32_t)(mi * 16 * W_RS);
            ldsm_x4(wfr[mi][0], wfr[mi][1], wfr[mi][2], wfr[mi][3], ad);
        }
        uint32_t bfr[2][4];
        {
            const uint32_t hbase = sbase + OFF_B + stg + bOff;
            ldsm_x4_t(bfr[0][0], bfr[0][1], bfr[0][2], bfr[0][3], hbase + ch0);
            ldsm_x4_t(bfr[1][0], bfr[1][1], bfr[1][2], bfr[1][3], hbase + ch1);
        }

        if (kt + 5 < NK) issueW(kt + 5, (kt + 5) % NSTG);
        else             cp_commit();

        // ---- 16 mma, all independent accumulators ----
#pragma unroll
        for (int mi = 0; mi < 4; mi++)
#pragma unroll
            for (int nj = 0; nj < 2; nj++)
#pragma unroll
                for (int h = 0; h < 2; h++)
                    mma_f16(acc[mi][nj * 2 + h], wfr[mi],
                            bfr[nj][2 * h], bfr[nj][2 * h + 1]);
    }

    // ---- epilogue ----
    const int g = lane >> 2;
    const int t = lane & 3;
    const int b    = mBase >> 12;
    const int pbB  = (mBase & 4095) + wn;
    float* outB = out + (size_t)b * COUT * NPIX;

#pragma unroll
    for (int mi = 0; mi < 4; mi++) {
        int c0 = coutBase + wm + mi * 16 + g;
        int c1 = c0 + 8;
        float bv0 = __ldg(&bias[c0]);
        float bv1 = __ldg(&bias[c1]);
        float* r0 = outB + (size_t)c0 * NPIX + pbB;
        float* r1 = outB + (size_t)c1 * NPIX + pbB;
#pragma unroll
        for (int ni = 0; ni < 4; ni++) {
            int pcol = ni * 8 + 2 * t;
            float2 v0 = make_float2(acc[mi][ni][0] + bv0, acc[mi][ni][1] + bv0);
            float2 v1 = make_float2(acc[mi][ni][2] + bv1, acc[mi][ni][3] + bv1);
            *reinterpret_cast<float2*>(r0 + pcol) = v0;
            *reinterpret_cast<float2*>(r1 + pcol) = v1;
        }
    }
}

// ===========================================================================
extern "C" void kernel_launch(void* const* d_in, const int* in_sizes, int n_in,
                              void* d_out, int out_size)
{
    const float* x        = (const float*)d_in[0];
    const float* weight   = (const float*)d_in[1];
    const float* bias     = (const float*)d_in[2];
    const float* offset_w = (const float*)d_in[3];
    const float* offset_b = (const float*)d_in[4];
    float* out = (float*)d_out;

    cudaFuncSetAttribute(gemm_kernel,
                         cudaFuncAttributeMaxDynamicSharedMemorySize, GEMM_SMEM);

    // 0) weight -> fp16
    wconv_kernel<<<(COUT * KDIM + 255) / 256, 256>>>(weight);

    // 1) offset conv partials (8 channel slices of 32)
    dim3 ogrid(MTOT / 256, 8);
    offset_partial_kernel<<<ogrid, 256>>>(x, offset_w);

    // 2) finalize offsets (kk-split grid for occupancy)
    dim3 fgrid(MTOT / 256, KKN);
    offset_final_kernel<<<fgrid, 256>>>(offset_b);

    // 3) bilinear gather -> fp16 A matrix (c-split x2)
    dim3 ggrid(MTOT / 256, KKN, 2);
    gather_kernel<<<ggrid, 256>>>(x);

    // 4) HMMA GEMM + bias (BK=16, 6-stage, single barrier per stage)
    dim3 mgrid(MTOT / 128, COUT / 128);
    gemm_kernel<<<mgrid, 256, GEMM_SMEM>>>(bias, out);
}

// round 15
// speedup vs baseline: 1.1337x; 1.0894x over previous
#include <cuda_runtime.h>
#include <cuda_fp16.h>
#include <cstdint>

// ---------------------------------------------------------------------------
// DCNv2: B=8, Cin=Cout=256, H=W=64, K=3, S=1, P=1, D=1
// Pipeline (R14 base + GEMM occupancy 2):
//   0) wconv:           weight -> fp16 [cout][k]
//   1) offset_partial:  8 channel-slices (32 ch) of 3x3 offset conv -> g_om8
//   2) offset_final:    per-(m,kk) sum of ONLY the 3 needed channels (grid x9)
//   3) gather:          bilinear sample (fp32 taps) * mask -> A fp16 [k][m]
//   4) gemm:            mma.sync m16n8k16 f16 single term, BK=16,
//                       6-stage cp.async ring, one barrier per stage,
//                       __launch_bounds__(256, 2) -> 2 CTAs/SM hides
//                       stage-boundary bubbles (R14 audit: GEMM at 55% of
//                       HMMA floor purely from occ-1 serialization)
// Error budget (calibrated): A + W fp16 roundings -> rel_err 2.93e-4.
// (tcgen05 unavailable: harness PTX targets compute_103.
//  R9: fused gather at 1 CTA/SM exposes scattered-LDG latency.
//  R12: 16-slice offset split + BK=32 ring regressed.
//  R13: fp16-tap gather neutral (not byte-bound); reverted.)
// ---------------------------------------------------------------------------

#define BDIM   8
#define CIN    256
#define COUT   256
#define KKN    9
#define NPIX   4096
#define MTOT   32768
#define KDIM   2304

// ------------------------- scratch (device globals) ------------------------
__device__ float g_py[BDIM * KKN * NPIX];
__device__ float g_px[BDIM * KKN * NPIX];
__device__ float g_pm[BDIM * KKN * NPIX];
__device__ float g_om8[8 * 27 * MTOT];
__device__ __half g_Ah[(size_t)KDIM * MTOT];       // [k][m]  (151 MB)
__device__ __half g_Wh[COUT * KDIM];               // [n][k]

// ------------------------- PTX wrappers ------------------------------------
static __device__ __forceinline__ uint32_t smem_u32(const void* p) {
    return (uint32_t)__cvta_generic_to_shared(p);
}
static __device__ __forceinline__ void ldsm_x4(uint32_t& r0, uint32_t& r1,
                                               uint32_t& r2, uint32_t& r3,
                                               uint32_t addr) {
    asm volatile("ldmatrix.sync.aligned.m8n8.x4.shared.b16 {%0,%1,%2,%3}, [%4];"
                 : "=r"(r0), "=r"(r1), "=r"(r2), "=r"(r3) : "r"(addr));
}
static __device__ __forceinline__ void ldsm_x4_t(uint32_t& r0, uint32_t& r1,
                                                 uint32_t& r2, uint32_t& r3,
                                                 uint32_t addr) {
    asm volatile("ldmatrix.sync.aligned.m8n8.x4.trans.shared.b16 {%0,%1,%2,%3}, [%4];"
                 : "=r"(r0), "=r"(r1), "=r"(r2), "=r"(r3) : "r"(addr));
}
static __device__ __forceinline__ void mma_f16(float* d, const uint32_t* a,
                                               uint32_t b0, uint32_t b1) {
    asm volatile(
        "mma.sync.aligned.m16n8k16.row.col.f32.f16.f16.f32 "
        "{%0,%1,%2,%3},{%4,%5,%6,%7},{%8,%9},{%0,%1,%2,%3};"
        : "+f"(d[0]), "+f"(d[1]), "+f"(d[2]), "+f"(d[3])
        : "r"(a[0]), "r"(a[1]), "r"(a[2]), "r"(a[3]), "r"(b0), "r"(b1));
}
static __device__ __forceinline__ void cpasync16(uint32_t dst, const void* src) {
    asm volatile("cp.async.cg.shared.global [%0], [%1], 16;"
                 :: "r"(dst), "l"(src) : "memory");
}
static __device__ __forceinline__ void cp_commit() {
    asm volatile("cp.async.commit_group;" ::: "memory");
}
static __device__ __forceinline__ void cp_wait4() {
    asm volatile("cp.async.wait_group 4;" ::: "memory");
}

// ===========================================================================
// Kernel 0: weight -> fp16
// ===========================================================================
__global__ __launch_bounds__(256) void wconv_kernel(const float* __restrict__ w)
{
    int i = blockIdx.x * 256 + threadIdx.x;
    if (i < COUT * KDIM)
        g_Wh[i] = __float2half_rn(w[i]);
}

// ===========================================================================
// Kernel 1: offset conv partial (one 32-channel slice per blockIdx.y, 8 total)
// ===========================================================================
__global__ __launch_bounds__(256) void offset_partial_kernel(
    const float* __restrict__ x,
    const float* __restrict__ ow)
{
    const int tid = threadIdx.x;
    const int m   = blockIdx.x * 256 + tid;
    const int sl  = blockIdx.y;                 // slice 0..7
    const int b   = m >> 12;
    const int p   = m & 4095;
    const int ho  = p >> 6;
    const int wo  = p & 63;

    __shared__ __align__(16) float ws[32 * 9 * 28];

    float acc[28];
#pragma unroll
    for (int i = 0; i < 28; i++) acc[i] = 0.f;

    const bool r0ok = (ho > 0), r2ok = (ho < 63);
    const bool c0ok = (wo > 0), c2ok = (wo < 63);

    const int c0 = sl * 32;
    for (int idx = tid; idx < 27 * 32 * 9; idx += 256) {
        int oc  = idx / 288;
        int rem = idx % 288;
        int c   = rem / 9;
        int kk  = rem % 9;
        ws[c * 252 + kk * 28 + oc] = ow[(oc * CIN + c0 + c) * 9 + kk];
    }
    for (int idx = tid; idx < 288; idx += 256) {
        int c = idx / 9, kk = idx % 9;
        ws[c * 252 + kk * 28 + 27] = 0.f;
    }
    __syncthreads();

#pragma unroll 1
    for (int c = 0; c < 32; ++c) {
        const float* xc = x + ((size_t)(b * CIN + c0 + c)) * NPIX;
        float xv[9];
#pragma unroll
        for (int ki = 0; ki < 3; ki++) {
#pragma unroll
            for (int kj = 0; kj < 3; kj++) {
                bool rok = (ki == 0) ? r0ok : ((ki == 2) ? r2ok : true);
                bool cok = (kj == 0) ? c0ok : ((kj == 2) ? c2ok : true);
                int yy = ho - 1 + ki, xx = wo - 1 + kj;
                xv[ki * 3 + kj] = (rok && cok) ? xc[yy * 64 + xx] : 0.f;
            }
        }
#pragma unroll
        for (int kk = 0; kk < 9; kk++) {
            float xvk = xv[kk];
            const float4* wrow =
                reinterpret_cast<const float4*>(&ws[c * 252 + kk * 28]);
#pragma unroll
            for (int o4 = 0; o4 < 7; o4++) {
                float4 w = wrow[o4];
                acc[o4 * 4 + 0] += xvk * w.x;
                acc[o4 * 4 + 1] += xvk * w.y;
                acc[o4 * 4 + 2] += xvk * w.z;
                acc[o4 * 4 + 3] += xvk * w.w;
            }
        }
    }

#pragma unroll
    for (int i = 0; i < 27; i++)
        g_om8[((size_t)(sl * 27 + i)) * MTOT + m] = acc[i];
}

// ===========================================================================
// Kernel 2: offset finalize (kk-split: grid 128 x 9)
//   Each thread handles one (m, kk): needs only channels 2kk, 2kk+1, 18+kk.
// ===========================================================================
__global__ __launch_bounds__(256) void offset_final_kernel(
    const float* __restrict__ ob)
{
    const int m  = blockIdx.x * 256 + threadIdx.x;
    const int kk = blockIdx.y;
    const int b  = m >> 12;
    const int p  = m & 4095;
    const int ho = p >> 6;
    const int wo = p & 63;

    float sdy = 0.f, sdx = 0.f, smv = 0.f;
#pragma unroll
    for (int sl = 0; sl < 8; sl++) {
        const float* base = g_om8 + (size_t)sl * 27 * MTOT + m;
        sdy += base[(size_t)(2 * kk)     * MTOT];
        sdx += base[(size_t)(2 * kk + 1) * MTOT];
        smv += base[(size_t)(18 + kk)    * MTOT];
    }

    float dy = sdy + ob[2 * kk];
    float dx = sdx + ob[2 * kk + 1];
    float mv = smv + ob[18 + kk];
    mv = 1.f / (1.f + __expf(-mv));
    int ki = kk / 3, kj = kk % 3;
    float pyv = dy + (float)(ho - 1 + ki);
    float pxv = dx + (float)(wo - 1 + kj);
    int o = ((b * 9 + kk) << 12) + p;
    g_py[o] = pyv;
    g_px[o] = pxv;
    g_pm[o] = mv;
}

// ===========================================================================
// Kernel 3: bilinear gather -> A fp16, K-major g_Ah[k = c*9+kk][m]
//   c-split: blockIdx.z in {0,1}, 128 channels each  (R11-proven)
// ===========================================================================
__global__ __launch_bounds__(256) void gather_kernel(const float* __restrict__ x)
{
    const int tid = threadIdx.x;
    const int m   = blockIdx.x * 256 + tid;
    const int kk  = blockIdx.y;
    const int cs  = blockIdx.z * 128;
    const int b   = m >> 12;
    const int p   = m & 4095;

    const int o = ((b * 9 + kk) << 12) + p;
    const float pyv = g_py[o];
    const float pxv = g_px[o];
    const float mv  = g_pm[o];

    float y0f = floorf(pyv), x0f = floorf(pxv);
    float wy1 = pyv - y0f, wx1 = pxv - x0f;
    float wy0 = 1.f - wy1, wx0 = 1.f - wx1;
    int y0 = (int)y0f, x0 = (int)x0f;
    int y1 = y0 + 1,   x1 = x0 + 1;

    float w00 = wy0 * wx0 * mv, w01 = wy0 * wx1 * mv;
    float w10 = wy1 * wx0 * mv, w11 = wy1 * wx1 * mv;
    if (y0 < 0 || y0 > 63) { w00 = 0.f; w01 = 0.f; }
    if (y1 < 0 || y1 > 63) { w10 = 0.f; w11 = 0.f; }
    if (x0 < 0 || x0 > 63) { w00 = 0.f; w10 = 0.f; }
    if (x1 < 0 || x1 > 63) { w01 = 0.f; w11 = 0.f; }

    int y0c = min(max(y0, 0), 63), y1c = min(max(y1, 0), 63);
    int x0c = min(max(x0, 0), 63), x1c = min(max(x1, 0), 63);
    const int o00 = y0c * 64 + x0c, o01 = y0c * 64 + x1c;
    const int o10 = y1c * 64 + x0c, o11 = y1c * 64 + x1c;

    const float* xb = x + (size_t)(b * CIN + cs) * NPIX;
    const size_t base = (size_t)kk * MTOT + m + (size_t)cs * 9 * MTOT;

#pragma unroll 8
    for (int c = 0; c < 128; ++c) {
        const float* xc = xb + (size_t)c * NPIX;
        float v = w00 * xc[o00] + w01 * xc[o01] +
                  w10 * xc[o10] + w11 * xc[o11];
        g_Ah[base + (size_t)c * 9 * MTOT] = __float2half_rn(v);
    }
}

// ===========================================================================
// Kernel 4: HMMA GEMM  out[cout][m] = sum_k W[cout][k] * A[k][m]
//   Block tile 128 cout x 128 pixels, 8 warps (warp tile 64x32).
//   6-stage cp.async ring (BK=16, 10 KB/stage), one barrier per stage.
//   16 mma per warp per stage, single fp16 term.
//   __launch_bounds__(256, 2): 2 CTAs/SM (120 KB smem, <=128 regs) so the
//   co-resident CTA's mma stream hides stage-boundary bubbles.
// ===========================================================================
#define NSTG      6
#define W_RS      48
#define STG_BYTES 10240
#define OFF_B     6144
#define GEMM_SMEM (NSTG * STG_BYTES)   // 61440

__global__ __launch_bounds__(256, 2) void gemm_kernel(
    const float* __restrict__ bias,
    float* __restrict__ out)
{
    extern __shared__ __align__(1024) unsigned char smem[];
    const uint32_t sbase = smem_u32(smem);
    const int tid  = threadIdx.x;
    const int warp = tid >> 5;
    const int lane = tid & 31;
    const int mBase    = blockIdx.x * 128;   // pixel base
    const int coutBase = blockIdx.y * 128;

    // ------ staging indices ------
    const int am = tid >> 1;          // W: cout row in tile 0..127
    const int ah = tid & 1;           // W: k half (8 fp16 = 16B)
    const int bk = tid >> 4;          // A: k row 0..15
    const int bc = tid & 15;          // A: pixel chunk (8 fp16)

    const char* gW = reinterpret_cast<const char*>(
        g_Wh + (size_t)(coutBase + am) * KDIM);
    const char* gB = reinterpret_cast<const char*>(
        g_Ah + (size_t)bk * MTOT + mBase + bc * 8);

    const uint32_t aSts = (uint32_t)(am * W_RS + ah * 16);
    const uint32_t bSts = (uint32_t)(bk * 256 + ((bc ^ (bk & 7)) * 16));

    // ------ fragment addresses ------
    const int wm = (warp >> 2) * 64;
    const int wn = (warp & 3) * 32;
    const uint32_t aAddrBase = sbase +
        (uint32_t)((wm + (lane & 15)) * W_RS + ((lane >> 4) & 1) * 16);
    const int kRow   = (lane & 7) + ((lane >> 3) & 1) * 8;
    const int chBase = (wn >> 3) + ((lane >> 4) & 1);
    const uint32_t bOff = (uint32_t)(kRow * 256);
    const uint32_t ch0 = (uint32_t)(((chBase + 0) ^ (kRow & 7)) * 16);
    const uint32_t ch1 = (uint32_t)(((chBase + 2) ^ (kRow & 7)) * 16);

    float acc[4][4][4];
#pragma unroll
    for (int i = 0; i < 4; i++)
#pragma unroll
        for (int j = 0; j < 4; j++)
#pragma unroll
            for (int r = 0; r < 4; r++) acc[i][j][r] = 0.f;

    const int NK = KDIM / 16;   // 144

    auto issueW = [&](int kt, int buf) {
        const uint32_t sb = sbase + (uint32_t)(buf * STG_BYTES);
        cpasync16(sb + aSts,         gW + (size_t)kt * 32 + (size_t)ah * 16);
        cpasync16(sb + OFF_B + bSts, gB + (size_t)kt * 16 * MTOT * 2);
        cp_commit();
    };

#pragma unroll
    for (int kt = 0; kt < 5; ++kt) issueW(kt, kt);

    for (int kt = 0; kt < NK; ++kt) {
        const int buf = kt % NSTG;
        cp_wait4();
        __syncthreads();   // sole barrier: orders both ring reuse and A-arrival

        const uint32_t stg = (uint32_t)(buf * STG_BYTES);

        uint32_t wfr[4][4];
#pragma unroll
        for (int mi = 0; mi < 4; mi++) {
            uint32_t ad = aAddrBase + stg + (uint32_t)(mi * 16 * W_RS);
            ldsm_x4(wfr[mi][0], wfr[mi][1], wfr[mi][2], wfr[mi][3], ad);
        }
        uint32_t bfr[2][4];
        {
            const uint32_t hbase = sbase + OFF_B + stg + bOff;
            ldsm_x4_t(bfr[0][0], bfr[0][1], bfr[0][2], bfr[0][3], hbase + ch0);
            ldsm_x4_t(bfr[1][0], bfr[1][1], bfr[1][2], bfr[1][3], hbase + ch1);
        }

        if (kt + 5 < NK) issueW(kt + 5, (kt + 5) % NSTG);
        else             cp_commit();

        // ---- 16 mma, all independent accumulators ----
#pragma unroll
        for (int mi = 0; mi < 4; mi++)
#pragma unroll
            for (int nj = 0; nj < 2; nj++)
#pragma unroll
                for (int h = 0; h < 2; h++)
                    mma_f16(acc[mi][nj * 2 + h], wfr[mi],
                            bfr[nj][2 * h], bfr[nj][2 * h + 1]);
    }

    // ---- epilogue ----
    const int g = lane >> 2;
    const int t = lane & 3;
    const int b    = mBase >> 12;
    const int pbB  = (mBase & 4095) + wn;
    float* outB = out + (size_t)b * COUT * NPIX;

#pragma unroll
    for (int mi = 0; mi < 4; mi++) {
        int c0 = coutBase + wm + mi * 16 + g;
        int c1 = c0 + 8;
        float bv0 = __ldg(&bias[c0]);
        float bv1 = __ldg(&bias[c1]);
        float* r0 = outB + (size_t)c0 * NPIX + pbB;
        float* r1 = outB + (size_t)c1 * NPIX + pbB;
#pragma unroll
        for (int ni = 0; ni < 4; ni++) {
            int pcol = ni * 8 + 2 * t;
            float2 v0 = make_float2(acc[mi][ni][0] + bv0, acc[mi][ni][1] + bv0);
            float2 v1 = make_float2(acc[mi][ni][2] + bv1, acc[mi][ni][3] + bv1);
            *reinterpret_cast<float2*>(r0 + pcol) = v0;
            *reinterpret_cast<float2*>(r1 + pcol) = v1;
        }
    }
}

// ===========================================================================
extern "C" void kernel_launch(void* const* d_in, const int* in_sizes, int n_in,
                              void* d_out, int out_size)
{
    const float* x        = (const float*)d_in[0];
    const float* weight   = (const float*)d_in[1];
    const float* bias     = (const float*)d_in[2];
    const float* offset_w = (const float*)d_in[3];
    const float* offset_b = (const float*)d_in[4];
    float* out = (float*)d_out;

    cudaFuncSetAttribute(gemm_kernel,
                         cudaFuncAttributeMaxDynamicSharedMemorySize, GEMM_SMEM);

    // 0) weight -> fp16
    wconv_kernel<<<(COUT * KDIM + 255) / 256, 256>>>(weight);

    // 1) offset conv partials (8 channel slices of 32)
    dim3 ogrid(MTOT / 256, 8);
    offset_partial_kernel<<<ogrid, 256>>>(x, offset_w);

    // 2) finalize offsets (kk-split grid for occupancy)
    dim3 fgrid(MTOT / 256, KKN);
    offset_final_kernel<<<fgrid, 256>>>(offset_b);

    // 3) bilinear gather -> fp16 A matrix (c-split x2)
    dim3 ggrid(MTOT / 256, KKN, 2);
    gather_kernel<<<ggrid, 256>>>(x);

    // 4) HMMA GEMM + bias (BK=16, 6-stage, 2 CTAs/SM)
    dim3 mgrid(MTOT / 128, COUT / 128);
    gemm_kernel<<<mgrid, 256, GEMM_SMEM>>>(bias, out);
}